// round 2
// baseline (speedup 1.0000x reference)
#include <cuda_runtime.h>
#include <math.h>
#include <stdint.h>

#define LQn 900
#define Bn 16
#define Dn 256
#define NHn 8
#define HDn 32
#define DFFn 1024
#define LVn 13294
#define NROWS (LQn*Bn)   /* 14400 */

// ---------------- scratch (device globals; no runtime allocation) ----------
__device__ float g_x   [NROWS*Dn];
__device__ float g_qk  [NROWS*2*Dn];
__device__ float g_v   [NROWS*Dn];
__device__ float g_attn[NROWS*Dn];
__device__ float g_sa  [NROWS*Dn];
__device__ float g_tgt1[NROWS*Dn];
__device__ float g_q2  [NROWS*Dn];
__device__ float g_vproj[(size_t)LVn*Bn*Dn];
__device__ float g_off [NROWS*256];
__device__ float g_awl [NROWS*128];
__device__ float g_ms  [NROWS*Dn];
__device__ float g_ca  [NROWS*Dn];
__device__ float g_tgt2[NROWS*Dn];
__device__ float g_ffn [(size_t)NROWS*DFFn];
__device__ float g_t2  [NROWS*Dn];

// ---------------- elementwise add ------------------------------------------
__global__ void add_kernel(const float* __restrict__ a, const float* __restrict__ b,
                           float* __restrict__ o, int n)
{
    int i = blockIdx.x * 256 + threadIdx.x;
    if (i < n) o[i] = a[i] + b[i];
}

// ---------------- SGEMM: C[M,N] = A[M,K] * W[N,K]^T + bias, optional ReLU ---
template<bool RELU>
__global__ void __launch_bounds__(256) gemm_bias(
    const float* __restrict__ A, const float* __restrict__ W,
    const float* __restrict__ bias, float* __restrict__ C,
    int M, int N, int K)
{
    __shared__ float As[16][128];
    __shared__ float Bs[16][64];
    const int tid = threadIdx.x;
    const int tx = tid & 15, ty = tid >> 4;
    const int bm = blockIdx.y * 128;
    const int bn = blockIdx.x * 64;

    float acc[8][4];
#pragma unroll
    for (int i = 0; i < 8; i++)
#pragma unroll
        for (int j = 0; j < 4; j++) acc[i][j] = 0.f;

    for (int k0 = 0; k0 < K; k0 += 16) {
        // A tile: 128x16 = 512 float4, 2 per thread (transpose into As[k][m])
#pragma unroll
        for (int it = 0; it < 2; it++) {
            int idx = tid + it * 256;
            int row = idx >> 2;
            int c4  = (idx & 3) << 2;
            float4 v = make_float4(0.f, 0.f, 0.f, 0.f);
            int gr = bm + row;
            if (gr < M)
                v = *reinterpret_cast<const float4*>(&A[(size_t)gr * K + k0 + c4]);
            As[c4 + 0][row] = v.x; As[c4 + 1][row] = v.y;
            As[c4 + 2][row] = v.z; As[c4 + 3][row] = v.w;
        }
        // W tile: 64x16 = 256 float4, 1 per thread
        {
            int row = tid >> 2;
            int c4  = (tid & 3) << 2;
            float4 v = *reinterpret_cast<const float4*>(&W[(size_t)(bn + row) * K + k0 + c4]);
            Bs[c4 + 0][row] = v.x; Bs[c4 + 1][row] = v.y;
            Bs[c4 + 2][row] = v.z; Bs[c4 + 3][row] = v.w;
        }
        __syncthreads();
#pragma unroll
        for (int k = 0; k < 16; k++) {
            float a[8], b[4];
#pragma unroll
            for (int i = 0; i < 8; i++) a[i] = As[k][ty * 8 + i];
#pragma unroll
            for (int j = 0; j < 4; j++) b[j] = Bs[k][tx * 4 + j];
#pragma unroll
            for (int i = 0; i < 8; i++)
#pragma unroll
                for (int j = 0; j < 4; j++)
                    acc[i][j] = fmaf(a[i], b[j], acc[i][j]);
        }
        __syncthreads();
    }
#pragma unroll
    for (int i = 0; i < 8; i++) {
        int row = bm + ty * 8 + i;
        if (row >= M) continue;
#pragma unroll
        for (int j = 0; j < 4; j++) {
            int col = bn + tx * 4 + j;
            float r = acc[i][j] + bias[col];
            if (RELU) r = fmaxf(r, 0.f);
            C[(size_t)row * N + col] = r;
        }
    }
}

// ---------------- self attention -------------------------------------------
// grid: (ceil(900/8), NH, B), block 256 = 8 warps, one query per warp.
// qk layout: row r=(q*B+b), 512 cols: q at [h*32+d], k at [256+h*32+d].
__global__ void __launch_bounds__(256) attn_kernel(
    const float* __restrict__ qk, const float* __restrict__ v,
    float* __restrict__ out)
{
    const int b = blockIdx.z, h = blockIdx.y;
    const int warp = threadIdx.x >> 5, lane = threadIdx.x & 31;
    const int q = blockIdx.x * 8 + warp;

    __shared__ float Ks[64][33];
    __shared__ float logits[8][912];
    __shared__ float Qs[8][32];

    const float scale = 0.176776695296636881f;  // 1/sqrt(32)
    if (q < LQn)
        Qs[warp][lane] = qk[(size_t)(q * Bn + b) * 512 + h * 32 + lane] * scale;

    // ---- QK^T ----
    for (int j0 = 0; j0 < LQn; j0 += 64) {
        int jn = min(64, LQn - j0);
        __syncthreads();
        for (int idx = threadIdx.x; idx < jn * 32; idx += 256) {
            int jj = idx >> 5, d = idx & 31;
            Ks[jj][d] = qk[(size_t)((j0 + jj) * Bn + b) * 512 + 256 + h * 32 + d];
        }
        __syncthreads();
        if (q < LQn) {
            for (int jj = lane; jj < jn; jj += 32) {
                float s = 0.f;
#pragma unroll
                for (int d = 0; d < 32; d++) s = fmaf(Qs[warp][d], Ks[jj][d], s);
                logits[warp][j0 + jj] = s;
            }
        }
    }
    __syncthreads();

    // ---- softmax (per warp) ----
    float inv = 0.f;
    if (q < LQn) {
        float m = -1e30f;
        for (int j = lane; j < LQn; j += 32) m = fmaxf(m, logits[warp][j]);
#pragma unroll
        for (int o = 16; o; o >>= 1) m = fmaxf(m, __shfl_xor_sync(~0u, m, o));
        float s = 0.f;
        for (int j = lane; j < LQn; j += 32) {
            float e = __expf(logits[warp][j] - m);
            logits[warp][j] = e;
            s += e;
        }
#pragma unroll
        for (int o = 16; o; o >>= 1) s += __shfl_xor_sync(~0u, s, o);
        inv = 1.f / s;
    }

    // ---- attn @ V ----
    float acc = 0.f;
    for (int j0 = 0; j0 < LQn; j0 += 64) {
        int jn = min(64, LQn - j0);
        __syncthreads();
        for (int idx = threadIdx.x; idx < jn * 32; idx += 256) {
            int jj = idx >> 5, d = idx & 31;
            Ks[jj][d] = v[(size_t)((j0 + jj) * Bn + b) * 256 + h * 32 + d];
        }
        __syncthreads();
        if (q < LQn) {
            for (int jj = 0; jj < jn; jj++)
                acc = fmaf(logits[warp][j0 + jj], Ks[jj][lane], acc);
        }
    }
    if (q < LQn)
        out[(size_t)(q * Bn + b) * 256 + h * 32 + lane] = acc * inv;
}

// ---------------- MS deformable attention sampling --------------------------
__device__ __forceinline__ float msda_tap(
    const float* __restrict__ vp, int b, int h, int lane,
    int start, int W, int H, int xi, int yi)
{
    bool valid = (xi >= 0) && (xi < W) && (yi >= 0) && (yi < H);
    int xc = min(max(xi, 0), W - 1);
    int yc = min(max(yi, 0), H - 1);
    size_t pos = (size_t)start + (size_t)yc * W + xc;
    float v = vp[(pos * Bn + b) * 256 + h * 32 + lane];
    return valid ? v : 0.f;
}

// grid 14400 blocks x 256 threads: warp per (b,q,h), lane per channel d.
__global__ void __launch_bounds__(256) msda_kernel(
    const float* __restrict__ ref, const float* __restrict__ off,
    const float* __restrict__ awl, const float* __restrict__ vp,
    const int* __restrict__ shapes, const int* __restrict__ lsi,
    float* __restrict__ out)
{
    int wg   = blockIdx.x * 8 + (threadIdx.x >> 5);
    int lane = threadIdx.x & 31;
    int h = wg & 7;
    int t = wg >> 3;
    int q = t % LQn;
    int b = t / LQn;
    size_t r = (size_t)q * Bn + b;

    // attention-weight softmax over 16 (lvl,pt)
    float aw[16];
    const float* awp = awl + r * 128 + h * 16;
    float mx = -1e30f;
#pragma unroll
    for (int p = 0; p < 16; p++) { aw[p] = awp[p]; mx = fmaxf(mx, aw[p]); }
    float s = 0.f;
#pragma unroll
    for (int p = 0; p < 16; p++) { aw[p] = __expf(aw[p] - mx); s += aw[p]; }
    float invs = 1.f / s;

    const float* offp = off + r * 256 + h * 32;
    const float* refp = ref + r * 8;

    float acc = 0.f;
#pragma unroll
    for (int lvl = 0; lvl < 4; lvl++) {
        int H = shapes[lvl * 2 + 0];
        int W = shapes[lvl * 2 + 1];
        int start = lsi[lvl];
        float rx = refp[lvl * 2 + 0];
        float ry = refp[lvl * 2 + 1];
#pragma unroll
        for (int p = 0; p < 4; p++) {
            float ox = offp[(lvl * 4 + p) * 2 + 0];
            float oy = offp[(lvl * 4 + p) * 2 + 1];
            float x = rx * (float)W + ox - 0.5f;
            float y = ry * (float)H + oy - 0.5f;
            float x0f = floorf(x), y0f = floorf(y);
            float wx = x - x0f, wy = y - y0f;
            int x0 = (int)x0f, y0 = (int)y0f;
            float w = aw[lvl * 4 + p] * invs;
            float v00 = msda_tap(vp, b, h, lane, start, W, H, x0,     y0);
            float v01 = msda_tap(vp, b, h, lane, start, W, H, x0 + 1, y0);
            float v10 = msda_tap(vp, b, h, lane, start, W, H, x0,     y0 + 1);
            float v11 = msda_tap(vp, b, h, lane, start, W, H, x0 + 1, y0 + 1);
            float bil = (1.f - wx) * (1.f - wy) * v00 + wx * (1.f - wy) * v01
                      + (1.f - wx) * wy * v10 + wx * wy * v11;
            acc = fmaf(w, bil, acc);
        }
    }
    out[r * 256 + h * 32 + lane] = acc;
}

// ---------------- fused residual-add + LayerNorm (warp per row) -------------
__global__ void __launch_bounds__(256) add_ln_kernel(
    const float* __restrict__ a, const float* __restrict__ res,
    const float* __restrict__ g, const float* __restrict__ be,
    float* __restrict__ out,
    const float* __restrict__ pos, float* __restrict__ q2)
{
    int warp = threadIdx.x >> 5, lane = threadIdx.x & 31;
    int row = blockIdx.x * 8 + warp;
    if (row >= NROWS) return;
    size_t base = (size_t)row * 256;

    float v[8];
    float s = 0.f;
#pragma unroll
    for (int i = 0; i < 8; i++) {
        v[i] = a[base + i * 32 + lane] + res[base + i * 32 + lane];
        s += v[i];
    }
#pragma unroll
    for (int o = 16; o; o >>= 1) s += __shfl_xor_sync(~0u, s, o);
    float mean = s * (1.f / 256.f);
    float vs = 0.f;
#pragma unroll
    for (int i = 0; i < 8; i++) { float d = v[i] - mean; vs += d * d; }
#pragma unroll
    for (int o = 16; o; o >>= 1) vs += __shfl_xor_sync(~0u, vs, o);
    float inv = rsqrtf(vs * (1.f / 256.f) + 1e-5f);
#pragma unroll
    for (int i = 0; i < 8; i++) {
        int c = i * 32 + lane;
        float y = (v[i] - mean) * inv * g[c] + be[c];
        out[base + c] = y;
        if (q2) q2[base + c] = y + pos[base + c];
    }
}

// ---------------- launch ----------------------------------------------------
static void launch_gemm(const float* A, const float* W, const float* bias,
                        float* C, int M, int N, int K, bool relu)
{
    dim3 grid((N + 63) / 64, (M + 127) / 128);
    if (relu) gemm_bias<true ><<<grid, 256>>>(A, W, bias, C, M, N, K);
    else      gemm_bias<false><<<grid, 256>>>(A, W, bias, C, M, N, K);
}

extern "C" void kernel_launch(void* const* d_in, const int* in_sizes, int n_in,
                              void* d_out, int out_size)
{
    const float* tgt  = (const float*)d_in[0];
    const float* pos  = (const float*)d_in[1];
    const float* refp = (const float*)d_in[2];
    const float* mem  = (const float*)d_in[3];
    const float* in_w = (const float*)d_in[4];
    const float* in_b = (const float*)d_in[5];
    const float* ow   = (const float*)d_in[6];
    const float* ob   = (const float*)d_in[7];
    const float* so_w = (const float*)d_in[8];
    const float* so_b = (const float*)d_in[9];
    const float* aw_w = (const float*)d_in[10];
    const float* aw_b = (const float*)d_in[11];
    const float* v_w  = (const float*)d_in[12];
    const float* v_b  = (const float*)d_in[13];
    const float* mo_w = (const float*)d_in[14];
    const float* mo_b = (const float*)d_in[15];
    const float* l1_w = (const float*)d_in[16];
    const float* l1_b = (const float*)d_in[17];
    const float* l2_w = (const float*)d_in[18];
    const float* l2_b = (const float*)d_in[19];
    const float* n1g  = (const float*)d_in[20];
    const float* n1b  = (const float*)d_in[21];
    const float* n2g  = (const float*)d_in[22];
    const float* n2b  = (const float*)d_in[23];
    const float* n3g  = (const float*)d_in[24];
    const float* n3b  = (const float*)d_in[25];
    const int* shapes = (const int*)d_in[26];
    const int* lsi    = (const int*)d_in[27];
    float* out = (float*)d_out;

    float *x, *qk, *v, *at, *sa, *t1, *q2, *vp, *off, *awl, *ms, *ca, *t2, *ffn, *tt2;
    cudaGetSymbolAddress((void**)&x,   g_x);
    cudaGetSymbolAddress((void**)&qk,  g_qk);
    cudaGetSymbolAddress((void**)&v,   g_v);
    cudaGetSymbolAddress((void**)&at,  g_attn);
    cudaGetSymbolAddress((void**)&sa,  g_sa);
    cudaGetSymbolAddress((void**)&t1,  g_tgt1);
    cudaGetSymbolAddress((void**)&q2,  g_q2);
    cudaGetSymbolAddress((void**)&vp,  g_vproj);
    cudaGetSymbolAddress((void**)&off, g_off);
    cudaGetSymbolAddress((void**)&awl, g_awl);
    cudaGetSymbolAddress((void**)&ms,  g_ms);
    cudaGetSymbolAddress((void**)&ca,  g_ca);
    cudaGetSymbolAddress((void**)&t2,  g_tgt2);
    cudaGetSymbolAddress((void**)&ffn, g_ffn);
    cudaGetSymbolAddress((void**)&tt2, g_t2);

    const int M = NROWS;              // 14400 rows (LQ*B)
    const int MV = LVn * Bn;          // 212704 rows (value projection)

    // 1) x = tgt + pos
    add_kernel<<<(M * Dn + 255) / 256, 256>>>(tgt, pos, x, M * Dn);

    // 2) self-attention
    launch_gemm(x,   in_w,            in_b,       qk, M, 512, 256, false); // q|k
    launch_gemm(tgt, in_w + 512 * 256, in_b + 512, v,  M, 256, 256, false); // v
    {
        dim3 grid((LQn + 7) / 8, NHn, Bn);
        attn_kernel<<<grid, 256>>>(qk, v, at);
    }
    launch_gemm(at, ow, ob, sa, M, 256, 256, false);

    // 3) tgt1 = LN(tgt + sa, norm2); q2 = tgt1 + pos
    add_ln_kernel<<<(M + 7) / 8, 256>>>(tgt, sa, n2g, n2b, t1, pos, q2);

    // 4) MS-deformable cross attention
    launch_gemm(mem, v_w,  v_b,  vp,  MV, 256, 256, false);  // value proj
    launch_gemm(q2,  so_w, so_b, off, M,  256, 256, false);  // sampling offsets
    launch_gemm(q2,  aw_w, aw_b, awl, M,  128, 256, false);  // attn weight logits
    // one warp per (b,q,h): B*LQ*NH = 115200 warps -> 14400 blocks of 8 warps
    msda_kernel<<<(M * NHn) / 8, 256>>>(refp, off, awl, vp, shapes, lsi, ms);
    launch_gemm(ms, mo_w, mo_b, ca, M, 256, 256, false);

    // 5) tgt2 = LN(tgt1 + ca, norm1)
    add_ln_kernel<<<(M + 7) / 8, 256>>>(t1, ca, n1g, n1b, t2, nullptr, nullptr);

    // 6) FFN
    launch_gemm(t2,  l1_w, l1_b, ffn, M, 1024, 256,  true);
    launch_gemm(ffn, l2_w, l2_b, tt2, M, 256,  1024, false);

    // 7) out = LN(tgt2 + t2, norm3)
    add_ln_kernel<<<(M + 7) / 8, 256>>>(t2, tt2, n3g, n3b, out, nullptr, nullptr);
}

// round 3
// speedup vs baseline: 1.4736x; 1.4736x over previous
#include <cuda_runtime.h>
#include <math.h>
#include <stdint.h>

#define LQn 900
#define Bn 16
#define Dn 256
#define NHn 8
#define HDn 32
#define DFFn 1024
#define LVn 13294
#define NROWS (LQn*Bn)   /* 14400 */

// ---------------- scratch (device globals; no runtime allocation) ----------
__device__ float g_x   [NROWS*Dn];
__device__ float g_qk  [NROWS*2*Dn];
__device__ float g_v   [NROWS*Dn];
__device__ float g_attn[NROWS*Dn];
__device__ float g_sa  [NROWS*Dn];
__device__ float g_tgt1[NROWS*Dn];
__device__ float g_q2  [NROWS*Dn];
__device__ float g_vproj[(size_t)LVn*Bn*Dn];
__device__ float g_off [NROWS*256];
__device__ float g_awl [NROWS*128];
__device__ float g_ms  [NROWS*Dn];
__device__ float g_ca  [NROWS*Dn];
__device__ float g_tgt2[NROWS*Dn];
__device__ float g_ffn [(size_t)NROWS*DFFn];
__device__ float g_t2  [NROWS*Dn];

// ---------------- elementwise add ------------------------------------------
__global__ void add_kernel(const float* __restrict__ a, const float* __restrict__ b,
                           float* __restrict__ o, int n)
{
    int i = blockIdx.x * 256 + threadIdx.x;
    if (i < n) o[i] = a[i] + b[i];
}

// ---------------- TF32 tensor-core GEMM -------------------------------------
// C[M,N] = A[M,K] * W[N,K]^T + bias, optional ReLU.
// Tile 128x128x32, 256 threads = 8 warps in 4(M) x 2(N); warp tile 32x64.
// mma.sync.aligned.m16n8k8.row.col.f32.tf32.tf32.f32
// Smem padded to 36 floats/row so fragment loads are bank-conflict-free.

__device__ __forceinline__ uint32_t f2tf32(float f)
{
    uint32_t r;
    asm("cvt.rna.tf32.f32 %0, %1;" : "=r"(r) : "f"(f));
    return r;
}

__device__ __forceinline__ void mma_tf32(float c[4], const uint32_t a[4], const uint32_t b[2])
{
    asm volatile(
        "mma.sync.aligned.m16n8k8.row.col.f32.tf32.tf32.f32 "
        "{%0,%1,%2,%3}, {%4,%5,%6,%7}, {%8,%9}, {%0,%1,%2,%3};"
        : "+f"(c[0]), "+f"(c[1]), "+f"(c[2]), "+f"(c[3])
        : "r"(a[0]), "r"(a[1]), "r"(a[2]), "r"(a[3]), "r"(b[0]), "r"(b[1]));
}

template<bool RELU>
__global__ void __launch_bounds__(256) gemm_tc(
    const float* __restrict__ A, const float* __restrict__ W,
    const float* __restrict__ bias, float* __restrict__ C,
    int M, int N, int K)
{
    __shared__ uint32_t As[128][36];   // [m][k], tf32 bits
    __shared__ uint32_t Bs[128][36];   // [n][k], tf32 bits

    const int tid  = threadIdx.x;
    const int lane = tid & 31;
    const int warp = tid >> 5;
    const int wm = (warp >> 1) * 32;   // warp M origin in tile
    const int wn = (warp & 1) * 64;    // warp N origin in tile
    const int bm = blockIdx.y * 128;
    const int bn = blockIdx.x * 128;

    const int grp = lane >> 2;         // 0..7
    const int tig = lane & 3;          // 0..3

    float acc[2][8][4];
#pragma unroll
    for (int mi = 0; mi < 2; mi++)
#pragma unroll
        for (int ni = 0; ni < 8; ni++)
#pragma unroll
            for (int r = 0; r < 4; r++) acc[mi][ni][r] = 0.f;

    for (int k0 = 0; k0 < K; k0 += 32) {
        // load A tile 128x32 (4 float4 per thread), convert to tf32, store [m][k]
#pragma unroll
        for (int it = 0; it < 4; it++) {
            int idx = tid + it * 256;
            int row = idx >> 3;
            int kc  = (idx & 7) << 2;
            float4 v = make_float4(0.f, 0.f, 0.f, 0.f);
            int gr = bm + row;
            if (gr < M)
                v = *reinterpret_cast<const float4*>(&A[(size_t)gr * K + k0 + kc]);
            As[row][kc + 0] = f2tf32(v.x);
            As[row][kc + 1] = f2tf32(v.y);
            As[row][kc + 2] = f2tf32(v.z);
            As[row][kc + 3] = f2tf32(v.w);
        }
        // load W tile 128x32
#pragma unroll
        for (int it = 0; it < 4; it++) {
            int idx = tid + it * 256;
            int row = idx >> 3;
            int kc  = (idx & 7) << 2;
            float4 v = *reinterpret_cast<const float4*>(&W[(size_t)(bn + row) * K + k0 + kc]);
            Bs[row][kc + 0] = f2tf32(v.x);
            Bs[row][kc + 1] = f2tf32(v.y);
            Bs[row][kc + 2] = f2tf32(v.z);
            Bs[row][kc + 3] = f2tf32(v.w);
        }
        __syncthreads();

#pragma unroll
        for (int k8 = 0; k8 < 4; k8++) {
            const int kk = k8 * 8;
            uint32_t a[2][4], b[8][2];
#pragma unroll
            for (int mi = 0; mi < 2; mi++) {
                int r0 = wm + mi * 16 + grp;
                a[mi][0] = As[r0    ][kk + tig];
                a[mi][1] = As[r0 + 8][kk + tig];
                a[mi][2] = As[r0    ][kk + tig + 4];
                a[mi][3] = As[r0 + 8][kk + tig + 4];
            }
#pragma unroll
            for (int ni = 0; ni < 8; ni++) {
                int n0 = wn + ni * 8 + grp;
                b[ni][0] = Bs[n0][kk + tig];
                b[ni][1] = Bs[n0][kk + tig + 4];
            }
#pragma unroll
            for (int mi = 0; mi < 2; mi++)
#pragma unroll
                for (int ni = 0; ni < 8; ni++)
                    mma_tf32(acc[mi][ni], a[mi], b[ni]);
        }
        __syncthreads();
    }

    // epilogue: bias (+ReLU), write C. c0/c1 at (row, col..col+1), c2/c3 at row+8.
#pragma unroll
    for (int mi = 0; mi < 2; mi++) {
        int row0 = bm + wm + mi * 16 + grp;
        int row1 = row0 + 8;
#pragma unroll
        for (int ni = 0; ni < 8; ni++) {
            int col = bn + wn + ni * 8 + tig * 2;
            float b0 = bias[col], b1 = bias[col + 1];
            float v0 = acc[mi][ni][0] + b0;
            float v1 = acc[mi][ni][1] + b1;
            float v2 = acc[mi][ni][2] + b0;
            float v3 = acc[mi][ni][3] + b1;
            if (RELU) {
                v0 = fmaxf(v0, 0.f); v1 = fmaxf(v1, 0.f);
                v2 = fmaxf(v2, 0.f); v3 = fmaxf(v3, 0.f);
            }
            if (row0 < M)
                *reinterpret_cast<float2*>(&C[(size_t)row0 * N + col]) = make_float2(v0, v1);
            if (row1 < M)
                *reinterpret_cast<float2*>(&C[(size_t)row1 * N + col]) = make_float2(v2, v3);
        }
    }
}

// ---------------- self attention -------------------------------------------
// grid: (ceil(900/8), NH, B), block 256 = 8 warps, one query per warp.
// qk layout: row r=(q*B+b), 512 cols: q at [h*32+d], k at [256+h*32+d].
__global__ void __launch_bounds__(256) attn_kernel(
    const float* __restrict__ qk, const float* __restrict__ v,
    float* __restrict__ out)
{
    const int b = blockIdx.z, h = blockIdx.y;
    const int warp = threadIdx.x >> 5, lane = threadIdx.x & 31;
    const int q = blockIdx.x * 8 + warp;

    __shared__ float Ks[64][33];
    __shared__ float logits[8][912];
    __shared__ float Qs[8][32];

    const float scale = 0.176776695296636881f;  // 1/sqrt(32)
    if (q < LQn)
        Qs[warp][lane] = qk[(size_t)(q * Bn + b) * 512 + h * 32 + lane] * scale;

    // ---- QK^T ----
    for (int j0 = 0; j0 < LQn; j0 += 64) {
        int jn = min(64, LQn - j0);
        __syncthreads();
        for (int idx = threadIdx.x; idx < jn * 32; idx += 256) {
            int jj = idx >> 5, d = idx & 31;
            Ks[jj][d] = qk[(size_t)((j0 + jj) * Bn + b) * 512 + 256 + h * 32 + d];
        }
        __syncthreads();
        if (q < LQn) {
            for (int jj = lane; jj < jn; jj += 32) {
                float s = 0.f;
#pragma unroll
                for (int d = 0; d < 32; d++) s = fmaf(Qs[warp][d], Ks[jj][d], s);
                logits[warp][j0 + jj] = s;
            }
        }
    }
    __syncthreads();

    // ---- softmax (per warp) ----
    float inv = 0.f;
    if (q < LQn) {
        float m = -1e30f;
        for (int j = lane; j < LQn; j += 32) m = fmaxf(m, logits[warp][j]);
#pragma unroll
        for (int o = 16; o; o >>= 1) m = fmaxf(m, __shfl_xor_sync(~0u, m, o));
        float s = 0.f;
        for (int j = lane; j < LQn; j += 32) {
            float e = __expf(logits[warp][j] - m);
            logits[warp][j] = e;
            s += e;
        }
#pragma unroll
        for (int o = 16; o; o >>= 1) s += __shfl_xor_sync(~0u, s, o);
        inv = 1.f / s;
    }

    // ---- attn @ V ----
    float acc = 0.f;
    for (int j0 = 0; j0 < LQn; j0 += 64) {
        int jn = min(64, LQn - j0);
        __syncthreads();
        for (int idx = threadIdx.x; idx < jn * 32; idx += 256) {
            int jj = idx >> 5, d = idx & 31;
            Ks[jj][d] = v[(size_t)((j0 + jj) * Bn + b) * 256 + h * 32 + d];
        }
        __syncthreads();
        if (q < LQn) {
            for (int jj = 0; jj < jn; jj++)
                acc = fmaf(logits[warp][j0 + jj], Ks[jj][lane], acc);
        }
    }
    if (q < LQn)
        out[(size_t)(q * Bn + b) * 256 + h * 32 + lane] = acc * inv;
}

// ---------------- MS deformable attention sampling --------------------------
__device__ __forceinline__ float msda_tap(
    const float* __restrict__ vp, int b, int h, int lane,
    int start, int W, int H, int xi, int yi)
{
    bool valid = (xi >= 0) && (xi < W) && (yi >= 0) && (yi < H);
    int xc = min(max(xi, 0), W - 1);
    int yc = min(max(yi, 0), H - 1);
    size_t pos = (size_t)start + (size_t)yc * W + xc;
    float v = vp[(pos * Bn + b) * 256 + h * 32 + lane];
    return valid ? v : 0.f;
}

// grid 14400 blocks x 256 threads: warp per (b,q,h), lane per channel d.
__global__ void __launch_bounds__(256) msda_kernel(
    const float* __restrict__ ref, const float* __restrict__ off,
    const float* __restrict__ awl, const float* __restrict__ vp,
    const int* __restrict__ shapes, const int* __restrict__ lsi,
    float* __restrict__ out)
{
    int wg   = blockIdx.x * 8 + (threadIdx.x >> 5);
    int lane = threadIdx.x & 31;
    int h = wg & 7;
    int t = wg >> 3;
    int q = t % LQn;
    int b = t / LQn;
    size_t r = (size_t)q * Bn + b;

    // attention-weight softmax over 16 (lvl,pt)
    float aw[16];
    const float* awp = awl + r * 128 + h * 16;
    float mx = -1e30f;
#pragma unroll
    for (int p = 0; p < 16; p++) { aw[p] = awp[p]; mx = fmaxf(mx, aw[p]); }
    float s = 0.f;
#pragma unroll
    for (int p = 0; p < 16; p++) { aw[p] = __expf(aw[p] - mx); s += aw[p]; }
    float invs = 1.f / s;

    const float* offp = off + r * 256 + h * 32;
    const float* refp = ref + r * 8;

    float acc = 0.f;
#pragma unroll
    for (int lvl = 0; lvl < 4; lvl++) {
        int H = shapes[lvl * 2 + 0];
        int W = shapes[lvl * 2 + 1];
        int start = lsi[lvl];
        float rx = refp[lvl * 2 + 0];
        float ry = refp[lvl * 2 + 1];
#pragma unroll
        for (int p = 0; p < 4; p++) {
            float ox = offp[(lvl * 4 + p) * 2 + 0];
            float oy = offp[(lvl * 4 + p) * 2 + 1];
            float x = rx * (float)W + ox - 0.5f;
            float y = ry * (float)H + oy - 0.5f;
            float x0f = floorf(x), y0f = floorf(y);
            float wx = x - x0f, wy = y - y0f;
            int x0 = (int)x0f, y0 = (int)y0f;
            float w = aw[lvl * 4 + p] * invs;
            float v00 = msda_tap(vp, b, h, lane, start, W, H, x0,     y0);
            float v01 = msda_tap(vp, b, h, lane, start, W, H, x0 + 1, y0);
            float v10 = msda_tap(vp, b, h, lane, start, W, H, x0,     y0 + 1);
            float v11 = msda_tap(vp, b, h, lane, start, W, H, x0 + 1, y0 + 1);
            float bil = (1.f - wx) * (1.f - wy) * v00 + wx * (1.f - wy) * v01
                      + (1.f - wx) * wy * v10 + wx * wy * v11;
            acc = fmaf(w, bil, acc);
        }
    }
    out[r * 256 + h * 32 + lane] = acc;
}

// ---------------- fused residual-add + LayerNorm (warp per row) -------------
__global__ void __launch_bounds__(256) add_ln_kernel(
    const float* __restrict__ a, const float* __restrict__ res,
    const float* __restrict__ g, const float* __restrict__ be,
    float* __restrict__ out,
    const float* __restrict__ pos, float* __restrict__ q2)
{
    int warp = threadIdx.x >> 5, lane = threadIdx.x & 31;
    int row = blockIdx.x * 8 + warp;
    if (row >= NROWS) return;
    size_t base = (size_t)row * 256;

    float v[8];
    float s = 0.f;
#pragma unroll
    for (int i = 0; i < 8; i++) {
        v[i] = a[base + i * 32 + lane] + res[base + i * 32 + lane];
        s += v[i];
    }
#pragma unroll
    for (int o = 16; o; o >>= 1) s += __shfl_xor_sync(~0u, s, o);
    float mean = s * (1.f / 256.f);
    float vs = 0.f;
#pragma unroll
    for (int i = 0; i < 8; i++) { float d = v[i] - mean; vs += d * d; }
#pragma unroll
    for (int o = 16; o; o >>= 1) vs += __shfl_xor_sync(~0u, vs, o);
    float inv = rsqrtf(vs * (1.f / 256.f) + 1e-5f);
#pragma unroll
    for (int i = 0; i < 8; i++) {
        int c = i * 32 + lane;
        float y = (v[i] - mean) * inv * g[c] + be[c];
        out[base + c] = y;
        if (q2) q2[base + c] = y + pos[base + c];
    }
}

// ---------------- launch ----------------------------------------------------
static void launch_gemm(const float* A, const float* W, const float* bias,
                        float* C, int M, int N, int K, bool relu)
{
    dim3 grid(N / 128, (M + 127) / 128);
    if (relu) gemm_tc<true ><<<grid, 256>>>(A, W, bias, C, M, N, K);
    else      gemm_tc<false><<<grid, 256>>>(A, W, bias, C, M, N, K);
}

extern "C" void kernel_launch(void* const* d_in, const int* in_sizes, int n_in,
                              void* d_out, int out_size)
{
    const float* tgt  = (const float*)d_in[0];
    const float* pos  = (const float*)d_in[1];
    const float* refp = (const float*)d_in[2];
    const float* mem  = (const float*)d_in[3];
    const float* in_w = (const float*)d_in[4];
    const float* in_b = (const float*)d_in[5];
    const float* ow   = (const float*)d_in[6];
    const float* ob   = (const float*)d_in[7];
    const float* so_w = (const float*)d_in[8];
    const float* so_b = (const float*)d_in[9];
    const float* aw_w = (const float*)d_in[10];
    const float* aw_b = (const float*)d_in[11];
    const float* v_w  = (const float*)d_in[12];
    const float* v_b  = (const float*)d_in[13];
    const float* mo_w = (const float*)d_in[14];
    const float* mo_b = (const float*)d_in[15];
    const float* l1_w = (const float*)d_in[16];
    const float* l1_b = (const float*)d_in[17];
    const float* l2_w = (const float*)d_in[18];
    const float* l2_b = (const float*)d_in[19];
    const float* n1g  = (const float*)d_in[20];
    const float* n1b  = (const float*)d_in[21];
    const float* n2g  = (const float*)d_in[22];
    const float* n2b  = (const float*)d_in[23];
    const float* n3g  = (const float*)d_in[24];
    const float* n3b  = (const float*)d_in[25];
    const int* shapes = (const int*)d_in[26];
    const int* lsi    = (const int*)d_in[27];
    float* out = (float*)d_out;

    float *x, *qk, *v, *at, *sa, *t1, *q2, *vp, *off, *awl, *ms, *ca, *t2, *ffn, *tt2;
    cudaGetSymbolAddress((void**)&x,   g_x);
    cudaGetSymbolAddress((void**)&qk,  g_qk);
    cudaGetSymbolAddress((void**)&v,   g_v);
    cudaGetSymbolAddress((void**)&at,  g_attn);
    cudaGetSymbolAddress((void**)&sa,  g_sa);
    cudaGetSymbolAddress((void**)&t1,  g_tgt1);
    cudaGetSymbolAddress((void**)&q2,  g_q2);
    cudaGetSymbolAddress((void**)&vp,  g_vproj);
    cudaGetSymbolAddress((void**)&off, g_off);
    cudaGetSymbolAddress((void**)&awl, g_awl);
    cudaGetSymbolAddress((void**)&ms,  g_ms);
    cudaGetSymbolAddress((void**)&ca,  g_ca);
    cudaGetSymbolAddress((void**)&t2,  g_tgt2);
    cudaGetSymbolAddress((void**)&ffn, g_ffn);
    cudaGetSymbolAddress((void**)&tt2, g_t2);

    const int M = NROWS;              // 14400 rows (LQ*B)
    const int MV = LVn * Bn;          // 212704 rows (value projection)

    // 1) x = tgt + pos
    add_kernel<<<(M * Dn + 255) / 256, 256>>>(tgt, pos, x, M * Dn);

    // 2) self-attention
    launch_gemm(x,   in_w,             in_b,       qk, M, 512, 256, false); // q|k
    launch_gemm(tgt, in_w + 512 * 256, in_b + 512, v,  M, 256, 256, false); // v
    {
        dim3 grid((LQn + 7) / 8, NHn, Bn);
        attn_kernel<<<grid, 256>>>(qk, v, at);
    }
    launch_gemm(at, ow, ob, sa, M, 256, 256, false);

    // 3) tgt1 = LN(tgt + sa, norm2); q2 = tgt1 + pos
    add_ln_kernel<<<(M + 7) / 8, 256>>>(tgt, sa, n2g, n2b, t1, pos, q2);

    // 4) MS-deformable cross attention
    launch_gemm(mem, v_w,  v_b,  vp,  MV, 256, 256, false);  // value proj
    launch_gemm(q2,  so_w, so_b, off, M,  256, 256, false);  // sampling offsets
    launch_gemm(q2,  aw_w, aw_b, awl, M,  128, 256, false);  // attn weight logits
    // one warp per (b,q,h): B*LQ*NH = 115200 warps -> 14400 blocks of 8 warps
    msda_kernel<<<(M * NHn) / 8, 256>>>(refp, off, awl, vp, shapes, lsi, ms);
    launch_gemm(ms, mo_w, mo_b, ca, M, 256, 256, false);

    // 5) tgt2 = LN(tgt1 + ca, norm1)
    add_ln_kernel<<<(M + 7) / 8, 256>>>(t1, ca, n1g, n1b, t2, nullptr, nullptr);

    // 6) FFN
    launch_gemm(t2,  l1_w, l1_b, ffn, M, 1024, 256,  true);
    launch_gemm(ffn, l2_w, l2_b, tt2, M, 256,  1024, false);

    // 7) out = LN(tgt2 + t2, norm3)
    add_ln_kernel<<<(M + 7) / 8, 256>>>(t2, tt2, n3g, n3b, out, nullptr, nullptr);
}